// round 14
// baseline (speedup 1.0000x reference)
#include <cuda_runtime.h>
#include <stdint.h>

#define BLOCK_SIZE 64
#define NUM_SELECTED 16
#define NB 128          // blocks per batch (8192/64)
#define B 32
#define D 512
#define S 8192

#define SEG_PER_BLK 4
#define THREADS 256
// float4 per block: 64*512/4 = 8192 ; per segment: 2048 ; per thread: 8
#define F4_PER_SEG ((BLOCK_SIZE * D / 4) / SEG_PER_BLK)
#define F4_PER_THREAD (F4_PER_SEG / THREADS)

// g_sel[bk] = selected block index + 1 (0 = not yet published).
// Payload lives in the flag word itself -> single-word dependency, no fence
// needed. Deterministic: same inputs -> same published values every replay.
__device__ int g_sel[B * NUM_SELECTED];

// FINAL (converged at the mixed-RW HBM roofline: ~6.4 TB/s combined traffic,
// 134 MB mandatory R+W). Fused single-launch kernel, 2048 CTAs x 256 thr:
//  - CTAs 0..31: exact top-k for batch b==cta (jax.lax.top_k ordering:
//    descending value, ties -> lower index), publish idx+1 via atomicExch.
//  - ALL CTAs: thread 0 polls g_sel[bk] with an atomic load (atomic keeps
//    the spin un-hoistable and L2-coherent; bare cached loads fault),
//    broadcast via smem + __syncthreads, then copy a contiguous 32 KB
//    segment with 8 front-batched float4 loads/stores per thread.
//    Producers are wave-1 resident (8/SM x 148 = 1184 >= 32) => no deadlock.
__global__ void __launch_bounds__(THREADS)
fused_gather_kernel(const float4* __restrict__ keys,
                    const float4* __restrict__ scores4,
                    float4* __restrict__ out) {
    int cta = blockIdx.x;
    int seg = cta & (SEG_PER_BLK - 1);
    int bk  = cta >> 2;                 // 0..511  (b*16 + k)
    int b   = bk >> 4;
    int t   = threadIdx.x;

    __shared__ int blk_s;

    // ---- producer phase: first 32 CTAs compute selection for batch = cta
    if (cta < B) {
        __shared__ float4 s4[NB / 4];
        if (t < NB / 4) s4[t] = __ldg(&scores4[cta * (NB / 4) + t]);
        __syncthreads();
        if (t < NB) {
            float v = ((const float*)s4)[t];
            int rank = 0;
#pragma unroll
            for (int j4 = 0; j4 < NB / 4; j4++) {
                float4 sj = s4[j4];
                int j = j4 * 4;
                rank += (sj.x > v) || (sj.x == v && (j + 0) < t);
                rank += (sj.y > v) || (sj.y == v && (j + 1) < t);
                rank += (sj.z > v) || (sj.z == v && (j + 2) < t);
                rank += (sj.w > v) || (sj.w == v && (j + 3) < t);
            }
            if (rank < NUM_SELECTED)
                atomicExch(&g_sel[cta * NUM_SELECTED + rank], t + 1);
        }
    }

    // ---- consumer: thread 0 fetches the selected block index (atomic poll)
    if (t == 0) {
        int val;
        do {
            val = atomicAdd(&g_sel[bk], 0);
        } while (val == 0);
        blk_s = val - 1;
    }
    __syncthreads();
    int blk = blk_s;

    const float4* src = keys
        + ((size_t)b * S + (size_t)blk * BLOCK_SIZE) * (D / 4)
        + (size_t)seg * F4_PER_SEG;
    float4* dst = out
        + (size_t)bk * (BLOCK_SIZE * D / 4)
        + (size_t)seg * F4_PER_SEG;

    // 8 float4 per thread, front-batched, plain loads/stores — the
    // configuration that measured best across the session.
    float4 v[F4_PER_THREAD];
#pragma unroll
    for (int i = 0; i < F4_PER_THREAD; i++)
        v[i] = src[t + i * THREADS];
#pragma unroll
    for (int i = 0; i < F4_PER_THREAD; i++)
        dst[t + i * THREADS] = v[i];
}

extern "C" void kernel_launch(void* const* d_in, const int* in_sizes, int n_in,
                              void* d_out, int out_size) {
    const float* keys = (const float*)d_in[0];
    const float* scores = (const float*)d_in[1];
    float* out = (float*)d_out;

    fused_gather_kernel<<<B * NUM_SELECTED * SEG_PER_BLK, THREADS>>>(
        (const float4*)keys, (const float4*)scores, (float4*)out);
}

// round 15
// speedup vs baseline: 1.0125x; 1.0125x over previous
#include <cuda_runtime.h>
#include <stdint.h>

#define BLOCK_SIZE 64
#define NUM_SELECTED 16
#define NB 128          // blocks per batch (8192/64)
#define B 32
#define D 512
#define S 8192

#define SEG_PER_BLK 4
#define THREADS 256
// float4 per block: 64*512/4 = 8192 ; per segment: 2048 ; per thread: 8
#define F4_PER_SEG ((BLOCK_SIZE * D / 4) / SEG_PER_BLK)
#define F4_PER_THREAD (F4_PER_SEG / THREADS)

// FINAL — converged at the mixed-RW memory roofline (134 MB mandatory
// traffic; kernel 20.7 us; all alternative organizations measured equal or
// worse across 14 rounds). Fused, dependency-free: each CTA recomputes the
// selection for its own (b, k) from the 128 batch scores (16 KB total,
// L2-broadcast after wave-1's first fetch), then copies its contiguous
// 32 KB segment with 8 front-batched float4 loads/stores per thread.
// Exact jax.lax.top_k ordering: descending value, ties -> lower index.
// grid = B * NUM_SELECTED * SEG_PER_BLK = 2048 CTAs.
__global__ void __launch_bounds__(THREADS)
fused_gather_kernel(const float4* __restrict__ keys,
                    const float4* __restrict__ scores4,
                    float4* __restrict__ out) {
    int cta = blockIdx.x;
    int seg = cta & (SEG_PER_BLK - 1);
    int bk  = cta >> 2;                 // 0..511  (b*16 + k)
    int b   = bk >> 4;
    int k   = bk & (NUM_SELECTED - 1);

    __shared__ float4 s4[NB / 4];
    __shared__ int blk_s;
    int t = threadIdx.x;

    if (t < NB / 4) s4[t] = __ldg(&scores4[b * (NB / 4) + t]);
    __syncthreads();

    // Rank of score t among the batch's 128 block scores (vectorized).
    if (t < NB) {
        float v = ((const float*)s4)[t];
        int rank = 0;
#pragma unroll
        for (int j4 = 0; j4 < NB / 4; j4++) {
            float4 sj = s4[j4];
            int j = j4 * 4;
            rank += (sj.x > v) || (sj.x == v && (j + 0) < t);
            rank += (sj.y > v) || (sj.y == v && (j + 1) < t);
            rank += (sj.z > v) || (sj.z == v && (j + 2) < t);
            rank += (sj.w > v) || (sj.w == v && (j + 3) < t);
        }
        if (rank == k) blk_s = t;
    }
    __syncthreads();
    int blk = blk_s;

    const float4* src = keys
        + ((size_t)b * S + (size_t)blk * BLOCK_SIZE) * (D / 4)
        + (size_t)seg * F4_PER_SEG;
    float4* dst = out
        + (size_t)bk * (BLOCK_SIZE * D / 4)
        + (size_t)seg * F4_PER_SEG;

    // 8 float4 per thread, front-batched, plain loads/stores — the
    // configuration that measured best across the session (regs ~32,
    // 8 CTAs/SM, occ ~80-90%).
    float4 v[F4_PER_THREAD];
#pragma unroll
    for (int i = 0; i < F4_PER_THREAD; i++)
        v[i] = src[t + i * THREADS];
#pragma unroll
    for (int i = 0; i < F4_PER_THREAD; i++)
        dst[t + i * THREADS] = v[i];
}

extern "C" void kernel_launch(void* const* d_in, const int* in_sizes, int n_in,
                              void* d_out, int out_size) {
    const float* keys = (const float*)d_in[0];
    const float* scores = (const float*)d_in[1];
    float* out = (float*)d_out;

    fused_gather_kernel<<<B * NUM_SELECTED * SEG_PER_BLK, THREADS>>>(
        (const float4*)keys, (const float4*)scores, (float4*)out);
}